// round 15
// baseline (speedup 1.0000x reference)
#include <cuda_runtime.h>
#include <cuda_bf16.h>
#include <math.h>
#include <stdint.h>

// ---------------------------------------------------------------------------
// FCOS head. Tower convs (256->256, 3x3) as implicit GEMM on warp-level
// mma.sync.m16n8k16 bf16 with 3-term hi/lo split (fp32-grade accuracy).
// NEW vs R14: GN-affine+ReLU+bf16-split hoisted into a separate memory-bound
// split_act pass that writes TRANSPOSED [b][px][256] hi/lo tensors, so the
// conv's B-fill is a contiguous 128B row copy (no cvt, no scatter).
// Heads (80/4/1 oc) scalar fp32 into final output layout (unchanged).
// ---------------------------------------------------------------------------

#define MAXBUF (8*256*15200)

__device__ float g_ycls[MAXBUF];                        // tower fp32 outputs
__device__ float g_ybox[MAXBUF];
__device__ __nv_bfloat16 g_fh[MAXBUF];                  // split feat (hi/lo), [b][px][256]
__device__ __nv_bfloat16 g_fl[MAXBUF];
__device__ __nv_bfloat16 g_th[MAXBUF];                  // split tower act (hi/lo)
__device__ __nv_bfloat16 g_tl[MAXBUF];
__device__ float g_stats[8*32*2];
__device__ float g_aff[2][2][8*256];                    // [slot][A|S][b*256+c]
__device__ __nv_bfloat16 g_wtc[8u*2u*36u*16384u];       // 8 layers x 2 ocTiles x 36 chunks x (hi|lo)

__device__ __forceinline__ uint32_t smem_u32(const void* p) {
    uint32_t a;
    asm("{ .reg .u64 t; cvta.to.shared.u64 t, %1; cvt.u32.u64 %0, t; }"
        : "=r"(a) : "l"(p));
    return a;
}
__device__ __forceinline__ void ldsm_x4(uint32_t& r0, uint32_t& r1,
                                        uint32_t& r2, uint32_t& r3, uint32_t addr) {
    asm volatile("ldmatrix.sync.aligned.m8n8.x4.shared.b16 {%0,%1,%2,%3}, [%4];"
                 : "=r"(r0), "=r"(r1), "=r"(r2), "=r"(r3) : "r"(addr));
}
__device__ __forceinline__ void mma_bf16(float* c, uint32_t a0, uint32_t a1,
                                         uint32_t a2, uint32_t a3,
                                         uint32_t b0, uint32_t b1) {
    asm volatile(
        "mma.sync.aligned.m16n8k16.row.col.f32.bf16.bf16.f32 "
        "{%0,%1,%2,%3}, {%4,%5,%6,%7}, {%8,%9}, {%0,%1,%2,%3};"
        : "+f"(c[0]), "+f"(c[1]), "+f"(c[2]), "+f"(c[3])
        : "r"(a0), "r"(a1), "r"(a2), "r"(a3), "r"(b0), "r"(b1));
}

#define PITCHB 144   // rows of 64 bf16 padded to 144 B (conflict-free ldmatrix)

// ---------------------------------------------------------------------------
// Weight reshape (unchanged layout): bf16 hi/lo tiles, [oc_r*64 + ic_c].
// ---------------------------------------------------------------------------
__global__ void reshape_wtc(const float* __restrict__ cls_w,
                            const float* __restrict__ box_w,
                            __nv_bfloat16* __restrict__ out)
{
    unsigned idx = blockIdx.x * blockDim.x + threadIdx.x;
    if (idx >= 8u*2u*36u*8192u) return;
    unsigned e = idx & 8191u;
    unsigned oc_r = e >> 6, ic_c = e & 63u;
    unsigned t = idx >> 13;
    unsigned chunk = t % 36u; t /= 36u;
    unsigned ot = t & 1u;  unsigned lay = t >> 1;
    unsigned k = chunk >> 2, icc = chunk & 3u;
    const float* src = (lay < 4) ? cls_w : box_w;
    unsigned l = lay & 3u;
    unsigned oc = ot * 128u + oc_r;
    unsigned ic = icc * 64u + ic_c;
    float w = src[(size_t)l * 256u * 2304u + (size_t)oc * 2304u + ic * 9u + k];
    __nv_bfloat16 hi = __float2bfloat16(w);
    __nv_bfloat16 lo = __float2bfloat16(w - __bfloat162float(hi));
    size_t base = ((size_t)(lay * 2u + ot) * 36u + chunk) * 16384u;
    out[base + oc_r * 64u + ic_c] = hi;
    out[base + 8192u + oc_r * 64u + ic_c] = lo;
}

// ---------------------------------------------------------------------------
// split_act: y [b][c][HW] fp32 -> (affine+relu if useAff) -> bf16 hi/lo split
// -> transposed [b][px][256]. Block 256, grid (ceil(HW/32), 8).
// ---------------------------------------------------------------------------
__global__ __launch_bounds__(256) void split_act(
    const float* __restrict__ y,
    const float* __restrict__ affA, const float* __restrict__ affS,
    __nv_bfloat16* __restrict__ oh, __nv_bfloat16* __restrict__ ol,
    int HW, int useAff)
{
    __shared__ float t[256][33];
    const int b  = blockIdx.y;
    const int p0 = blockIdx.x << 5;
    const int tid = threadIdx.x;
    // read: 8 c-rows per iter, 32 px coalesced
    {
        int cr = tid >> 5, pr = tid & 31;
        int p = p0 + pr;
        #pragma unroll 4
        for (int i = 0; i < 32; i++) {
            int c = cr + (i << 3);
            t[c][pr] = (p < HW) ? y[((size_t)b * 256 + c) * HW + p] : 0.f;
        }
    }
    __syncthreads();
    // write: px = tid>>3, 32 consecutive c per thread, bf162 stores
    {
        int pw = tid >> 3, c0 = (tid & 7) << 5;
        int p = p0 + pw;
        if (p < HW) {
            size_t ob = ((size_t)b * HW + p) * 256;
            #pragma unroll 8
            for (int c = c0; c < c0 + 32; c += 2) {
                float v0 = t[c][pw], v1 = t[c + 1][pw];
                if (useAff) {
                    v0 = fmaxf(fmaf(affA[b * 256 + c],     v0, affS[b * 256 + c]),     0.f);
                    v1 = fmaxf(fmaf(affA[b * 256 + c + 1], v1, affS[b * 256 + c + 1]), 0.f);
                }
                __nv_bfloat16 h0 = __float2bfloat16(v0);
                __nv_bfloat16 h1 = __float2bfloat16(v1);
                __nv_bfloat16 l0 = __float2bfloat16(v0 - __bfloat162float(h0));
                __nv_bfloat16 l1 = __float2bfloat16(v1 - __bfloat162float(h1));
                *(__nv_bfloat162*)(oh + ob + c) = __nv_bfloat162(h0, h1);
                *(__nv_bfloat162*)(ol + ob + c) = __nv_bfloat162(l0, l1);
            }
        }
    }
}

// ---------------------------------------------------------------------------
// Tower conv on mma.sync. Block 256 (8 warps), grid (ceil(HW/128), 8, 2).
// Warp = 64 oc x 32 px. B-fill is a contiguous 128B-row copy from the
// pre-split transposed activations.
// ---------------------------------------------------------------------------
__global__ __launch_bounds__(256, 2)
void conv_mma(const __nv_bfloat16* __restrict__ xh,
              const __nv_bfloat16* __restrict__ xl,
              const __nv_bfloat16* __restrict__ wt,
              const float* __restrict__ bias,
              float* __restrict__ y, float* __restrict__ stats, int H, int W)
{
    extern __shared__ char dsm[];
    const int HW = H * W;
    const int b  = blockIdx.y, ot = blockIdx.z;
    const int p0 = blockIdx.x << 7;
    const int tid = threadIdx.x, wid = tid >> 5, lane = tid & 31;

    uint32_t sraw = smem_u32(dsm);
    uint32_t sb = (sraw + 1023u) & ~1023u;
    char* base = dsm + (sb - sraw);
    const uint32_t uAhi = sb, uAlo = sb + 18432, uBhi = sb + 36864, uBlo = sb + 55296;
    char* pBhi = base + 36864;
    char* pBlo = base + 55296;
    float* s_out = (float*)base;               // 128 x 132 fp32 (epilogue reuse)

    const int j = tid & 127;                   // B row (pixel)
    const int pb = tid >> 7;                   // which 64B half of the row
    const int p = p0 + j;
    const bool inimg = p < HW;
    const int hh = p / W;
    const int ww = p - hh * W;

    const int warp_m = wid & 1;
    const int warp_n = wid >> 1;
    const int a_row = lane & 15, a_k8 = lane >> 4;
    const int b_sel = lane >> 3, b_row = lane & 7;

    float acc[4][4][4];
    #pragma unroll
    for (int mt = 0; mt < 4; mt++)
        #pragma unroll
        for (int nt = 0; nt < 4; nt++)
            #pragma unroll
            for (int q = 0; q < 4; q++) acc[mt][nt][q] = 0.f;

    for (int chunk = 0; chunk < 36; chunk++) {
        // ---- A fill: 2 planes x 1024 x 16B, rows repadded 128B -> 144B ----
        {
            const uint4* ws = (const uint4*)(wt + ((size_t)(ot * 36 + chunk) << 14));
            #pragma unroll
            for (int pl = 0; pl < 2; pl++) {
                char* dstp = base + pl * 18432;
                const uint4* srcp = ws + pl * 1024;
                #pragma unroll
                for (int i = 0; i < 4; i++) {
                    int u = tid + (i << 8);
                    int row = u >> 3, c8 = u & 7;
                    *(uint4*)(dstp + row * PITCHB + (c8 << 4)) = srcp[u];
                }
            }
        }
        // ---- B fill: contiguous 64B copy per (row, half) per plane ----
        {
            const int k  = chunk >> 2;
            const int dh = k / 3 - 1, dw = k - (k / 3) * 3 - 1;
            const int ic0 = (chunk & 3) << 6;
            const int h2 = hh + dh, w2 = ww + dw;
            const bool valid = inimg && (unsigned)h2 < (unsigned)H && (unsigned)w2 < (unsigned)W;
            uint4 vh[4], vl[4];
            if (valid) {
                const int pp2 = p + dh * W + dw;
                const size_t sofs = ((size_t)b * HW + pp2) * 256 + ic0 + (pb << 5);
                const uint4* sh = (const uint4*)(xh + sofs);
                const uint4* sl = (const uint4*)(xl + sofs);
                vh[0] = sh[0]; vh[1] = sh[1]; vh[2] = sh[2]; vh[3] = sh[3];
                vl[0] = sl[0]; vl[1] = sl[1]; vl[2] = sl[2]; vl[3] = sl[3];
            } else {
                #pragma unroll
                for (int q = 0; q < 4; q++) { vh[q] = make_uint4(0,0,0,0); vl[q] = make_uint4(0,0,0,0); }
            }
            uint4* dsth = (uint4*)(pBhi + j * PITCHB + (pb << 6));
            uint4* dstl = (uint4*)(pBlo + j * PITCHB + (pb << 6));
            dsth[0] = vh[0]; dsth[1] = vh[1]; dsth[2] = vh[2]; dsth[3] = vh[3];
            dstl[0] = vl[0]; dstl[1] = vl[1]; dstl[2] = vl[2]; dstl[3] = vl[3];
        }
        __syncthreads();

        // ---- compute: 4 k16-steps over the 64-ic chunk ----
        #pragma unroll
        for (int ks = 0; ks < 4; ks++) {
            uint32_t bh[8], bl[8];
            #pragma unroll
            for (int half = 0; half < 2; half++) {
                uint32_t nrow = warp_n * 32 + half * 16 + ((b_sel >> 1) << 3) + b_row;
                uint32_t koff = (ks << 4) + ((b_sel & 1) << 3);
                ldsm_x4(bh[half*4+0], bh[half*4+1], bh[half*4+2], bh[half*4+3],
                        uBhi + nrow * PITCHB + koff * 2);
                ldsm_x4(bl[half*4+0], bl[half*4+1], bl[half*4+2], bl[half*4+3],
                        uBlo + nrow * PITCHB + koff * 2);
            }
            #pragma unroll
            for (int mt = 0; mt < 4; mt++) {
                uint32_t arow = warp_m * 64 + mt * 16 + a_row;
                uint32_t koff = (ks << 4) + (a_k8 << 3);
                uint32_t ah0, ah1, ah2, ah3, al0, al1, al2, al3;
                ldsm_x4(ah0, ah1, ah2, ah3, uAhi + arow * PITCHB + koff * 2);
                ldsm_x4(al0, al1, al2, al3, uAlo + arow * PITCHB + koff * 2);
                #pragma unroll
                for (int nt = 0; nt < 4; nt++) {
                    uint32_t b0h = bh[(nt >> 1) * 4 + ((nt & 1) << 1)];
                    uint32_t b1h = bh[(nt >> 1) * 4 + ((nt & 1) << 1) + 1];
                    uint32_t b0l = bl[(nt >> 1) * 4 + ((nt & 1) << 1)];
                    uint32_t b1l = bl[(nt >> 1) * 4 + ((nt & 1) << 1) + 1];
                    mma_bf16(acc[mt][nt], ah0, ah1, ah2, ah3, b0h, b1h);
                    mma_bf16(acc[mt][nt], ah0, ah1, ah2, ah3, b0l, b1l);
                    mma_bf16(acc[mt][nt], al0, al1, al2, al3, b0h, b1h);
                }
            }
        }
        __syncthreads();
    }

    // ---- epilogue: acc + bias -> s_out -> stats -> coalesced store ----
    #pragma unroll
    for (int mt = 0; mt < 4; mt++) {
        int r1 = warp_m * 64 + mt * 16 + (lane >> 2);
        int r2 = r1 + 8;
        float bv1 = __ldg(bias + ot * 128 + r1);
        float bv2 = __ldg(bias + ot * 128 + r2);
        #pragma unroll
        for (int nt = 0; nt < 4; nt++) {
            int cb = warp_n * 32 + nt * 8 + ((lane & 3) << 1);
            s_out[r1 * 132 + cb]     = acc[mt][nt][0] + bv1;
            s_out[r1 * 132 + cb + 1] = acc[mt][nt][1] + bv1;
            s_out[r2 * 132 + cb]     = acc[mt][nt][2] + bv2;
            s_out[r2 * 132 + cb + 1] = acc[mt][nt][3] + bv2;
        }
    }
    __syncthreads();

    // stats: thread t handles half a row (row = t>>1, 64 cols)
    {
        int row = tid >> 1, half = tid & 1;
        float lsum = 0.f, lsq = 0.f;
        #pragma unroll 8
        for (int c = 0; c < 64; c++) {
            int col = (half << 6) + c;
            if (p0 + col < HW) {
                float v = s_out[row * 132 + col];
                lsum += v; lsq += v * v;
            }
        }
        #pragma unroll
        for (int o = 1; o <= 8; o <<= 1) {
            lsum += __shfl_xor_sync(0xffffffffu, lsum, o);
            lsq  += __shfl_xor_sync(0xffffffffu, lsq,  o);
        }
        if ((lane & 15) == 0) {
            int g = ot * 16 + (row >> 3);
            atomicAdd(&stats[(b * 32 + g) * 2 + 0], lsum);
            atomicAdd(&stats[(b * 32 + g) * 2 + 1], lsq);
        }
    }
    // coalesced store to y
    for (int i = 0; i < 64; i++) {
        int idx  = tid + (i << 8);
        int oc_r = idx >> 7, jj = idx & 127;
        int pp = p0 + jj;
        if (pp < HW)
            y[(((size_t)b << 8) + (ot << 7) + oc_r) * HW + pp] = s_out[oc_r * 132 + jj];
    }
}

// ---------------------------------------------------------------------------
// GN finalize: stats -> per-channel affine (a, s).
// ---------------------------------------------------------------------------
__global__ void gn_finalize(const float* __restrict__ stats,
                            const float* __restrict__ gamma,
                            const float* __restrict__ beta,
                            float* __restrict__ affA, float* __restrict__ affS,
                            float invCnt)
{
    int b = blockIdx.x;
    int c = threadIdx.x;
    int g = c >> 3;
    float sum = stats[(b * 32 + g) * 2 + 0];
    float sq  = stats[(b * 32 + g) * 2 + 1];
    float m   = sum * invCnt;
    float var = fmaf(sq, invCnt, -m * m);
    float rstd = rsqrtf(var + 1e-5f);
    float a = gamma[c] * rstd;
    affA[b * 256 + c] = a;
    affS[b * 256 + c] = fmaf(-m, a, beta[c]);
}

// ---------------------------------------------------------------------------
// Head conv: IC=256, OC in {80,1,4}. Affine+relu input. Direct final layout.
// ---------------------------------------------------------------------------
__global__ __launch_bounds__(256) void conv_head(
    const float* __restrict__ x, const float* __restrict__ w,
    const float* __restrict__ bias,
    const float* __restrict__ affA, const float* __restrict__ affS,
    float* __restrict__ out, size_t lvlOff, size_t TOT, int cbase,
    int OC, int H, int W, int doExp, const float* __restrict__ scales, int lvl)
{
    const int HW = H * W;
    const int b  = blockIdx.z;
    const int h0 = blockIdx.y << 3, w0 = blockIdx.x << 3;
    const int tid  = threadIdx.x;
    const int lane = tid & 3;
    const int pp   = tid >> 2;
    const int ph = pp >> 3, pw = pp & 7;

    __shared__ float s_in[8][10][12];
    __shared__ float s_w[8][9][80];

    float acc[20];
    const int noc = (OC + 3) >> 2;
    #pragma unroll
    for (int jj = 0; jj < 20; jj++) acc[jj] = 0.f;

    const float* xb = x + (size_t)b * 256 * HW;
    const float* aA = affA + b * 256;
    const float* aS = affS + b * 256;

    for (int c0 = 0; c0 < 256; c0 += 8) {
        for (int idx = tid; idx < 800; idx += 256) {
            int ic = idx / 100; int rr = idx - ic * 100;
            int r = rr / 10;    int c  = rr - r * 10;
            int ih = h0 - 1 + r, iw = w0 - 1 + c;
            float v = 0.f;
            if ((unsigned)ih < (unsigned)H && (unsigned)iw < (unsigned)W) {
                v = xb[(size_t)(c0 + ic) * HW + ih * W + iw];
                v = fmaxf(fmaf(aA[c0 + ic], v, aS[c0 + ic]), 0.f);
            }
            s_in[ic][r][c] = v;
        }
        int nw = OC * 72;
        for (int idx = tid; idx < nw; idx += 256) {
            int oc = idx / 72; int rem = idx - oc * 72;
            int ic = rem / 9;  int k   = rem - ic * 9;
            s_w[ic][k][oc] = w[(size_t)oc * 2304 + (c0 + ic) * 9 + k];
        }
        __syncthreads();

        #pragma unroll 2
        for (int ic = 0; ic < 8; ic++) {
            #pragma unroll
            for (int kh = 0; kh < 3; kh++) {
                #pragma unroll
                for (int kw = 0; kw < 3; kw++) {
                    float xv = s_in[ic][ph + kh][pw + kw];
                    int k = kh * 3 + kw;
                    for (int jj = 0; jj < noc; jj++)
                        acc[jj] = fmaf(xv, s_w[ic][k][(jj << 2) + lane], acc[jj]);
                }
            }
        }
        __syncthreads();
    }

    int hh = h0 + ph, ww = w0 + pw;
    if (hh < H && ww < W) {
        float sc = doExp ? scales[lvl] : 0.f;
        for (int jj = 0; jj < noc; jj++) {
            int oc = (jj << 2) + lane;
            if (oc < OC) {
                float v = acc[jj] + bias[oc];
                if (doExp) v = expf(sc * v);
                out[(size_t)b * TOT + lvlOff + (size_t)(cbase + oc) * HW + hh * W + ww] = v;
            }
        }
    }
}

// ---------------------------------------------------------------------------
// FCOS grid locations.
// ---------------------------------------------------------------------------
__global__ void locations_kernel(float* __restrict__ out, size_t base)
{
    const int Wl[5] = {152, 76, 38, 19, 10};
    const int Sl[5] = {8, 16, 32, 64, 128};
    const int sizes[5] = {15200, 3800, 950, 247, 70};
    int idx = blockIdx.x * blockDim.x + threadIdx.x;
    if (idx >= 20267) return;
    int l = 0, t = idx;
    while (l < 4 && t >= sizes[l]) { t -= sizes[l]; l++; }
    int yy = t / Wl[l], xx = t - yy * Wl[l];
    out[base + (size_t)idx * 2 + 0] = (float)(xx * Sl[l] + Sl[l] / 2);
    out[base + (size_t)idx * 2 + 1] = (float)(yy * Sl[l] + Sl[l] / 2);
}

// ---------------------------------------------------------------------------
// Host orchestration
// ---------------------------------------------------------------------------
extern "C" void kernel_launch(void* const* d_in, const int* in_sizes, int n_in,
                              void* d_out, int out_size)
{
    const float* feats[5] = {
        (const float*)d_in[0], (const float*)d_in[1], (const float*)d_in[2],
        (const float*)d_in[3], (const float*)d_in[4]};
    const float* cls_w    = (const float*)d_in[5];
    const float* cls_b    = (const float*)d_in[6];
    const float* cls_gn_g = (const float*)d_in[7];
    const float* cls_gn_b = (const float*)d_in[8];
    const float* box_w    = (const float*)d_in[9];
    const float* box_b    = (const float*)d_in[10];
    const float* box_gn_g = (const float*)d_in[11];
    const float* box_gn_b = (const float*)d_in[12];
    const float* logits_w = (const float*)d_in[13];
    const float* logits_b = (const float*)d_in[14];
    const float* ctr_w    = (const float*)d_in[15];
    const float* ctr_b    = (const float*)d_in[16];
    const float* reg_w    = (const float*)d_in[17];
    const float* reg_b    = (const float*)d_in[18];
    const float* scales   = (const float*)d_in[19];

    float *ycls, *ybox, *stats, *aff;
    __nv_bfloat16 *fh, *fl, *th, *tl, *wtc;
    cudaGetSymbolAddress((void**)&ycls, g_ycls);
    cudaGetSymbolAddress((void**)&ybox, g_ybox);
    cudaGetSymbolAddress((void**)&fh, g_fh);
    cudaGetSymbolAddress((void**)&fl, g_fl);
    cudaGetSymbolAddress((void**)&th, g_th);
    cudaGetSymbolAddress((void**)&tl, g_tl);
    cudaGetSymbolAddress((void**)&stats, g_stats);
    cudaGetSymbolAddress((void**)&aff, g_aff);
    cudaGetSymbolAddress((void**)&wtc, g_wtc);
    float* affA0 = aff;
    float* affS0 = aff + 2048;
    float* affA1 = aff + 4096;
    float* affS1 = aff + 6144;

    float* out = (float*)d_out;

    const int Hs[5] = {100, 50, 25, 13, 7};
    const int Ws[5] = {152, 76, 38, 19, 10};
    const size_t off85[5] = {0, 1292000, 1615000, 1695750, 1716745};
    const size_t TOT = 1722695;
    const size_t WLAY = (size_t)2 * 36 * 16384;      // bf16 per layer
    const int DYN = 73728 + 1024;

    cudaFuncSetAttribute(conv_mma, cudaFuncAttributeMaxDynamicSharedMemorySize, DYN);

    // one-time weight reshape into bf16 hi/lo tiles
    reshape_wtc<<<(8*2*36*8192 + 255) / 256, 256>>>(cls_w, box_w, wtc);

    for (int l = 0; l < 5; l++) {
        const int H = Hs[l], W = Ws[l], HW = H * W;
        const int ntiles = (HW + 127) / 128;
        dim3 grid(ntiles, 8, 2);
        dim3 gridS((HW + 31) / 32, 8);
        dim3 gridH((W + 7) / 8, (H + 7) / 8, 8);
        const float invCnt = 1.0f / (8.0f * (float)HW);

        // split raw feats (no affine/relu) into fh/fl
        split_act<<<gridS, 256>>>(feats[l], nullptr, nullptr, fh, fl, HW, 0);

        // ---- cls tower (layers 0-3, affine slot 0) ----
        {
            const __nv_bfloat16 *ch = fh, *cl = fl;
            for (int i = 0; i < 4; i++) {
                const __nv_bfloat16* wi = wtc + (size_t)i * WLAY;
                cudaMemsetAsync(stats, 0, 8 * 32 * 2 * sizeof(float), 0);
                conv_mma<<<grid, 256, DYN>>>(ch, cl, wi, cls_b + i * 256, ycls, stats, H, W);
                gn_finalize<<<8, 256>>>(stats, cls_gn_g + i * 256, cls_gn_b + i * 256,
                                        affA0, affS0, invCnt);
                if (i < 3) {
                    split_act<<<gridS, 256>>>(ycls, affA0, affS0, th, tl, HW, 1);
                    ch = th; cl = tl;
                }
            }
        }

        // ---- box tower (layers 4-7, affine slot 1) ----
        {
            const __nv_bfloat16 *ch = fh, *cl = fl;
            for (int i = 0; i < 4; i++) {
                const __nv_bfloat16* wi = wtc + (size_t)(4 + i) * WLAY;
                cudaMemsetAsync(stats, 0, 8 * 32 * 2 * sizeof(float), 0);
                conv_mma<<<grid, 256, DYN>>>(ch, cl, wi, box_b + i * 256, ybox, stats, H, W);
                gn_finalize<<<8, 256>>>(stats, box_gn_g + i * 256, box_gn_b + i * 256,
                                        affA1, affS1, invCnt);
                if (i < 3) {
                    split_act<<<gridS, 256>>>(ybox, affA1, affS1, th, tl, HW, 1);
                    ch = th; cl = tl;
                }
            }
        }

        // ---- heads: logits(80)@c0, reg(4)@c80 (exp), ctr(1)@c84 ----
        conv_head<<<gridH, 256>>>(ycls, logits_w, logits_b, affA0, affS0,
                                  out, off85[l], TOT, 0, 80, H, W, 0, scales, l);
        conv_head<<<gridH, 256>>>(ybox, reg_w, reg_b, affA1, affS1,
                                  out, off85[l], TOT, 80, 4, H, W, 1, scales, l);
        conv_head<<<gridH, 256>>>(ycls, ctr_w, ctr_b, affA0, affS0,
                                  out, off85[l], TOT, 84, 1, H, W, 0, scales, l);
    }

    locations_kernel<<<(20267 + 255) / 256, 256>>>(out, (size_t)8 * TOT);
}

// round 16
// speedup vs baseline: 1.0126x; 1.0126x over previous
#include <cuda_runtime.h>
#include <cuda_bf16.h>
#include <math.h>
#include <stdint.h>

// ---------------------------------------------------------------------------
// FCOS head. Tower convs (256->256, 3x3) as implicit GEMM on mma.sync bf16
// 3-term hi/lo split. R16: CTA = 256oc x 128px (ot merged), warp = 64oc x 64px
// (mt=4, nt=8) -> 85.3 B ldsm per HMMA (was 128) -> tensor ceiling ~85%.
// cp.async double-buffered A/B fills (221KB smem, 1 CTA/SM) hide fill latency.
// Activations pre-split to transposed [b][px][256] bf16 hi/lo by split_act.
// ---------------------------------------------------------------------------

#define MAXBUF (8*256*15200)

__device__ float g_ycls[MAXBUF];
__device__ float g_ybox[MAXBUF];
__device__ __nv_bfloat16 g_fh[MAXBUF];
__device__ __nv_bfloat16 g_fl[MAXBUF];
__device__ __nv_bfloat16 g_th[MAXBUF];
__device__ __nv_bfloat16 g_tl[MAXBUF];
__device__ float g_stats[8*32*2];
__device__ float g_aff[2][2][8*256];
__device__ __nv_bfloat16 g_wtc[8u*36u*2u*16384u];   // [lay][chunk][plane][256oc x 64ic]

__device__ __forceinline__ uint32_t smem_u32(const void* p) {
    uint32_t a;
    asm("{ .reg .u64 t; cvta.to.shared.u64 t, %1; cvt.u32.u64 %0, t; }"
        : "=r"(a) : "l"(p));
    return a;
}
__device__ __forceinline__ void ldsm_x4(uint32_t& r0, uint32_t& r1,
                                        uint32_t& r2, uint32_t& r3, uint32_t addr) {
    asm volatile("ldmatrix.sync.aligned.m8n8.x4.shared.b16 {%0,%1,%2,%3}, [%4];"
                 : "=r"(r0), "=r"(r1), "=r"(r2), "=r"(r3) : "r"(addr));
}
__device__ __forceinline__ void mma_bf16(float* c, const uint32_t* a,
                                         uint32_t b0, uint32_t b1) {
    asm volatile(
        "mma.sync.aligned.m16n8k16.row.col.f32.bf16.bf16.f32 "
        "{%0,%1,%2,%3}, {%4,%5,%6,%7}, {%8,%9}, {%0,%1,%2,%3};"
        : "+f"(c[0]), "+f"(c[1]), "+f"(c[2]), "+f"(c[3])
        : "r"(a[0]), "r"(a[1]), "r"(a[2]), "r"(a[3]), "r"(b0), "r"(b1));
}
__device__ __forceinline__ void cpa16(uint32_t dst, const void* src, uint32_t sz) {
    asm volatile("cp.async.ca.shared.global [%0], [%1], 16, %2;"
                 :: "r"(dst), "l"(src), "r"(sz) : "memory");
}
#define CPA_COMMIT() asm volatile("cp.async.commit_group;" ::: "memory")
#define CPA_WAIT0()  asm volatile("cp.async.wait_group 0;" ::: "memory")

#define PITCHB 144
#define ABYTES 73728              // 2 planes x 256 rows x 144
#define BBYTES 36864              // 2 planes x 128 rows x 144
#define BUFSZ  110592             // ABYTES + BBYTES
#define DYN    (2*BUFSZ + 1024)   // double buffer + align pad

// ---------------------------------------------------------------------------
// Weight reshape: fp32 w[lay][oc][ic*9+k] -> bf16 hi/lo:
// g_wtc[((lay*36+chunk)*2+plane)*16384 + oc*64 + ic_c], chunk = k*4 + icc.
// ---------------------------------------------------------------------------
__global__ void reshape_wtc(const float* __restrict__ cls_w,
                            const float* __restrict__ box_w,
                            __nv_bfloat16* __restrict__ out)
{
    unsigned idx = blockIdx.x * blockDim.x + threadIdx.x;   // 9,437,184
    if (idx >= 8u*36u*2u*16384u) return;
    unsigned e = idx & 16383u;
    unsigned oc = e >> 6, ic_c = e & 63u;
    unsigned t = idx >> 14;
    unsigned plane = t & 1u; t >>= 1;
    unsigned chunk = t % 36u;
    unsigned lay = t / 36u;
    unsigned k = chunk >> 2, icc = chunk & 3u;
    const float* src = (lay < 4) ? cls_w : box_w;
    unsigned l = lay & 3u;
    unsigned ic = icc * 64u + ic_c;
    float w = src[(size_t)l * 256u * 2304u + (size_t)oc * 2304u + ic * 9u + k];
    __nv_bfloat16 hi = __float2bfloat16(w);
    __nv_bfloat16 lo = __float2bfloat16(w - __bfloat162float(hi));
    out[idx] = plane ? lo : hi;
}

// ---------------------------------------------------------------------------
// split_act: y [b][c][HW] fp32 -> (affine+relu) -> bf16 hi/lo, transposed
// [b][px][256]. Block 256, grid (ceil(HW/32), 8).
// ---------------------------------------------------------------------------
__global__ __launch_bounds__(256) void split_act(
    const float* __restrict__ y,
    const float* __restrict__ affA, const float* __restrict__ affS,
    __nv_bfloat16* __restrict__ oh, __nv_bfloat16* __restrict__ ol,
    int HW, int useAff)
{
    __shared__ float t[256][33];
    const int b  = blockIdx.y;
    const int p0 = blockIdx.x << 5;
    const int tid = threadIdx.x;
    {
        int cr = tid >> 5, pr = tid & 31;
        int p = p0 + pr;
        #pragma unroll 4
        for (int i = 0; i < 32; i++) {
            int c = cr + (i << 3);
            t[c][pr] = (p < HW) ? y[((size_t)b * 256 + c) * HW + p] : 0.f;
        }
    }
    __syncthreads();
    {
        int pw = tid >> 3, c0 = (tid & 7) << 5;
        int p = p0 + pw;
        if (p < HW) {
            size_t ob = ((size_t)b * HW + p) * 256;
            #pragma unroll 8
            for (int c = c0; c < c0 + 32; c += 2) {
                float v0 = t[c][pw], v1 = t[c + 1][pw];
                if (useAff) {
                    v0 = fmaxf(fmaf(affA[b * 256 + c],     v0, affS[b * 256 + c]),     0.f);
                    v1 = fmaxf(fmaf(affA[b * 256 + c + 1], v1, affS[b * 256 + c + 1]), 0.f);
                }
                __nv_bfloat16 h0 = __float2bfloat16(v0);
                __nv_bfloat16 h1 = __float2bfloat16(v1);
                __nv_bfloat16 l0 = __float2bfloat16(v0 - __bfloat162float(h0));
                __nv_bfloat16 l1 = __float2bfloat16(v1 - __bfloat162float(h1));
                *(__nv_bfloat162*)(oh + ob + c) = __nv_bfloat162(h0, h1);
                *(__nv_bfloat162*)(ol + ob + c) = __nv_bfloat162(l0, l1);
            }
        }
    }
}

// ---------------------------------------------------------------------------
// Fill one buffer with chunk data via cp.async (A: weights, B: activations).
// ---------------------------------------------------------------------------
__device__ __forceinline__ void fill_chunk(
    uint32_t uBuf, int tid, int chunk,
    const __nv_bfloat16* __restrict__ wt,
    const __nv_bfloat16* __restrict__ xh, const __nv_bfloat16* __restrict__ xl,
    const int* hh4, const int* ww4, const int* pp4, const unsigned* inb4,
    int b, int HW, int H, int W)
{
    // A: 16 segs/thread
    const __nv_bfloat16* wc = wt + ((size_t)chunk << 15);
    #pragma unroll
    for (int i = 0; i < 16; i++) {
        int plane = i >> 3;
        int row = (tid >> 3) + ((i & 7) << 5);
        int s8 = tid & 7;
        uint32_t dst = uBuf + plane * 36864 + row * PITCHB + (s8 << 4);
        cpa16(dst, wc + (plane << 14) + (row << 6) + (s8 << 3), 16);
    }
    // B: 8 segs/thread, rows g+{0,32,64,96}
    const int k  = chunk >> 2;
    const int dh = k / 3 - 1, dw = k - (k / 3) * 3 - 1;
    const int ic0 = (chunk & 3) << 6;
    const int s8 = tid & 7;
    #pragma unroll
    for (int i = 0; i < 8; i++) {
        int plane = i >> 2;
        int q = i & 3;
        int row = (tid >> 3) + (q << 5);
        int h2 = hh4[q] + dh, w2 = ww4[q] + dw;
        unsigned valid = inb4[q] && (unsigned)h2 < (unsigned)H && (unsigned)w2 < (unsigned)W;
        const __nv_bfloat16* xp = plane ? xl : xh;
        const __nv_bfloat16* src = xp + ((size_t)(b * HW + (valid ? (pp4[q] + dh * W + dw) : 0)) << 8)
                                   + ic0 + (s8 << 3);
        uint32_t dst = uBuf + ABYTES + plane * 18432 + row * PITCHB + (s8 << 4);
        cpa16(dst, src, valid ? 16u : 0u);
    }
    CPA_COMMIT();
}

// ---------------------------------------------------------------------------
// Tower conv. Block 256 (8 warps), grid (ceil(HW/128), 8). CTA = 256oc x 128px.
// Warp = 64oc x 64px (mt=4, nt=8). Double-buffered cp.async fills.
// ---------------------------------------------------------------------------
__global__ __launch_bounds__(256)
void conv_mma(const __nv_bfloat16* __restrict__ xh,
              const __nv_bfloat16* __restrict__ xl,
              const __nv_bfloat16* __restrict__ wt,
              const float* __restrict__ bias,
              float* __restrict__ y, float* __restrict__ stats, int H, int W)
{
    extern __shared__ char dsm[];
    const int HW = H * W;
    const int b  = blockIdx.y;
    const int p0 = blockIdx.x << 7;
    const int tid = threadIdx.x, wid = tid >> 5, lane = tid & 31;

    uint32_t sraw = smem_u32(dsm);
    uint32_t sb = (sraw + 1023u) & ~1023u;
    char* base = dsm + (sb - sraw);
    float* s_out = (float*)base;               // 256 x 132 fp32 after compute

    // B row geometry for this thread's 4 fill rows
    int hh4[4], ww4[4], pp4[4];
    unsigned inb4[4];
    #pragma unroll
    for (int q = 0; q < 4; q++) {
        int row = (tid >> 3) + (q << 5);
        int p = p0 + row;
        pp4[q] = p;
        inb4[q] = (p < HW);
        int h = p / W;
        hh4[q] = h;
        ww4[q] = p - h * W;
    }

    const int warp_m = wid & 3;     // 4 x 64 oc
    const int warp_n = wid >> 2;    // 2 x 64 px
    const int a_row = lane & 15, a_k8 = lane >> 4;
    const int b_sel = lane >> 3, b_row = lane & 7;

    float acc[4][8][4];
    #pragma unroll
    for (int mt = 0; mt < 4; mt++)
        #pragma unroll
        for (int nt = 0; nt < 8; nt++)
            #pragma unroll
            for (int q = 0; q < 4; q++) acc[mt][nt][q] = 0.f;

    // prologue: fill chunk 0 into buf0
    fill_chunk(sb, tid, 0, wt, xh, xl, hh4, ww4, pp4, inb4, b, HW, H, W);

    for (int chunk = 0; chunk < 36; chunk++) {
        CPA_WAIT0();
        __syncthreads();
        if (chunk + 1 < 36)
            fill_chunk(sb + ((chunk + 1) & 1) * BUFSZ, tid, chunk + 1,
                       wt, xh, xl, hh4, ww4, pp4, inb4, b, HW, H, W);

        const uint32_t uA = sb + (chunk & 1) * BUFSZ;
        const uint32_t uB = uA + ABYTES;

        #pragma unroll
        for (int ks = 0; ks < 4; ks++) {
            uint32_t ah[4][4], al[4][4];
            const uint32_t koffA = ((ks << 4) + (a_k8 << 3)) << 1;
            #pragma unroll
            for (int mt = 0; mt < 4; mt++) {
                uint32_t arow = warp_m * 64 + mt * 16 + a_row;
                ldsm_x4(ah[mt][0], ah[mt][1], ah[mt][2], ah[mt][3],
                        uA + arow * PITCHB + koffA);
                ldsm_x4(al[mt][0], al[mt][1], al[mt][2], al[mt][3],
                        uA + 36864 + arow * PITCHB + koffA);
            }
            const uint32_t koffB = ((ks << 4) + ((b_sel & 1) << 3)) << 1;
            #pragma unroll
            for (int half = 0; half < 4; half++) {
                uint32_t nrow = warp_n * 64 + half * 16 + ((b_sel >> 1) << 3) + b_row;
                uint32_t bh[4], bl[4];
                ldsm_x4(bh[0], bh[1], bh[2], bh[3], uB + nrow * PITCHB + koffB);
                ldsm_x4(bl[0], bl[1], bl[2], bl[3], uB + 18432 + nrow * PITCHB + koffB);
                #pragma unroll
                for (int par = 0; par < 2; par++) {
                    const int nt = half * 2 + par;
                    uint32_t b0h = bh[par * 2], b1h = bh[par * 2 + 1];
                    uint32_t b0l = bl[par * 2], b1l = bl[par * 2 + 1];
                    #pragma unroll
                    for (int mt = 0; mt < 4; mt++) {
                        mma_bf16(acc[mt][nt], ah[mt], b0h, b1h);
                        mma_bf16(acc[mt][nt], ah[mt], b0l, b1l);
                        mma_bf16(acc[mt][nt], al[mt], b0h, b1h);
                    }
                }
            }
        }
        __syncthreads();
    }

    // ---- epilogue: acc + bias -> s_out (256 x 132) -> stats -> store ----
    #pragma unroll
    for (int mt = 0; mt < 4; mt++) {
        int r1 = warp_m * 64 + mt * 16 + (lane >> 2);
        int r2 = r1 + 8;
        float bv1 = __ldg(bias + r1);
        float bv2 = __ldg(bias + r2);
        #pragma unroll
        for (int nt = 0; nt < 8; nt++) {
            int cb = warp_n * 64 + nt * 8 + ((lane & 3) << 1);
            s_out[r1 * 132 + cb]     = acc[mt][nt][0] + bv1;
            s_out[r1 * 132 + cb + 1] = acc[mt][nt][1] + bv1;
            s_out[r2 * 132 + cb]     = acc[mt][nt][2] + bv2;
            s_out[r2 * 132 + cb + 1] = acc[mt][nt][3] + bv2;
        }
    }
    __syncthreads();

    // stats: thread = oc row, sum 128 px; reduce within 8-lane (8-oc) groups
    {
        float lsum = 0.f, lsq = 0.f;
        #pragma unroll 8
        for (int col = 0; col < 128; col++) {
            if (p0 + col < HW) {
                float v = s_out[tid * 132 + col];
                lsum += v; lsq += v * v;
            }
        }
        lsum += __shfl_xor_sync(0xffffffffu, lsum, 1);
        lsq  += __shfl_xor_sync(0xffffffffu, lsq,  1);
        lsum += __shfl_xor_sync(0xffffffffu, lsum, 2);
        lsq  += __shfl_xor_sync(0xffffffffu, lsq,  2);
        lsum += __shfl_xor_sync(0xffffffffu, lsum, 4);
        lsq  += __shfl_xor_sync(0xffffffffu, lsq,  4);
        if ((lane & 7) == 0) {
            int g = tid >> 3;
            atomicAdd(&stats[(b * 32 + g) * 2 + 0], lsum);
            atomicAdd(&stats[(b * 32 + g) * 2 + 1], lsq);
        }
    }
    // coalesced store: 256 oc x 128 px
    for (int i = 0; i < 128; i++) {
        int idx  = tid + (i << 8);
        int oc = idx >> 7, jj = idx & 127;
        int pp = p0 + jj;
        if (pp < HW)
            y[(((size_t)b << 8) + oc) * HW + pp] = s_out[oc * 132 + jj];
    }
}

// ---------------------------------------------------------------------------
// GN finalize: stats -> per-channel affine (a, s).
// ---------------------------------------------------------------------------
__global__ void gn_finalize(const float* __restrict__ stats,
                            const float* __restrict__ gamma,
                            const float* __restrict__ beta,
                            float* __restrict__ affA, float* __restrict__ affS,
                            float invCnt)
{
    int b = blockIdx.x;
    int c = threadIdx.x;
    int g = c >> 3;
    float sum = stats[(b * 32 + g) * 2 + 0];
    float sq  = stats[(b * 32 + g) * 2 + 1];
    float m   = sum * invCnt;
    float var = fmaf(sq, invCnt, -m * m);
    float rstd = rsqrtf(var + 1e-5f);
    float a = gamma[c] * rstd;
    affA[b * 256 + c] = a;
    affS[b * 256 + c] = fmaf(-m, a, beta[c]);
}

// ---------------------------------------------------------------------------
// Head conv: IC=256, OC in {80,1,4}. Affine+relu input. Direct final layout.
// ---------------------------------------------------------------------------
__global__ __launch_bounds__(256) void conv_head(
    const float* __restrict__ x, const float* __restrict__ w,
    const float* __restrict__ bias,
    const float* __restrict__ affA, const float* __restrict__ affS,
    float* __restrict__ out, size_t lvlOff, size_t TOT, int cbase,
    int OC, int H, int W, int doExp, const float* __restrict__ scales, int lvl)
{
    const int HW = H * W;
    const int b  = blockIdx.z;
    const int h0 = blockIdx.y << 3, w0 = blockIdx.x << 3;
    const int tid  = threadIdx.x;
    const int lane = tid & 3;
    const int pp   = tid >> 2;
    const int ph = pp >> 3, pw = pp & 7;

    __shared__ float s_in[8][10][12];
    __shared__ float s_w[8][9][80];

    float acc[20];
    const int noc = (OC + 3) >> 2;
    #pragma unroll
    for (int jj = 0; jj < 20; jj++) acc[jj] = 0.f;

    const float* xb = x + (size_t)b * 256 * HW;
    const float* aA = affA + b * 256;
    const float* aS = affS + b * 256;

    for (int c0 = 0; c0 < 256; c0 += 8) {
        for (int idx = tid; idx < 800; idx += 256) {
            int ic = idx / 100; int rr = idx - ic * 100;
            int r = rr / 10;    int c  = rr - r * 10;
            int ih = h0 - 1 + r, iw = w0 - 1 + c;
            float v = 0.f;
            if ((unsigned)ih < (unsigned)H && (unsigned)iw < (unsigned)W) {
                v = xb[(size_t)(c0 + ic) * HW + ih * W + iw];
                v = fmaxf(fmaf(aA[c0 + ic], v, aS[c0 + ic]), 0.f);
            }
            s_in[ic][r][c] = v;
        }
        int nw = OC * 72;
        for (int idx = tid; idx < nw; idx += 256) {
            int oc = idx / 72; int rem = idx - oc * 72;
            int ic = rem / 9;  int k   = rem - ic * 9;
            s_w[ic][k][oc] = w[(size_t)oc * 2304 + (c0 + ic) * 9 + k];
        }
        __syncthreads();

        #pragma unroll 2
        for (int ic = 0; ic < 8; ic++) {
            #pragma unroll
            for (int kh = 0; kh < 3; kh++) {
                #pragma unroll
                for (int kw = 0; kw < 3; kw++) {
                    float xv = s_in[ic][ph + kh][pw + kw];
                    int k = kh * 3 + kw;
                    for (int jj = 0; jj < noc; jj++)
                        acc[jj] = fmaf(xv, s_w[ic][k][(jj << 2) + lane], acc[jj]);
                }
            }
        }
        __syncthreads();
    }

    int hh = h0 + ph, ww = w0 + pw;
    if (hh < H && ww < W) {
        float sc = doExp ? scales[lvl] : 0.f;
        for (int jj = 0; jj < noc; jj++) {
            int oc = (jj << 2) + lane;
            if (oc < OC) {
                float v = acc[jj] + bias[oc];
                if (doExp) v = expf(sc * v);
                out[(size_t)b * TOT + lvlOff + (size_t)(cbase + oc) * HW + hh * W + ww] = v;
            }
        }
    }
}

// ---------------------------------------------------------------------------
// FCOS grid locations.
// ---------------------------------------------------------------------------
__global__ void locations_kernel(float* __restrict__ out, size_t base)
{
    const int Wl[5] = {152, 76, 38, 19, 10};
    const int Sl[5] = {8, 16, 32, 64, 128};
    const int sizes[5] = {15200, 3800, 950, 247, 70};
    int idx = blockIdx.x * blockDim.x + threadIdx.x;
    if (idx >= 20267) return;
    int l = 0, t = idx;
    while (l < 4 && t >= sizes[l]) { t -= sizes[l]; l++; }
    int yy = t / Wl[l], xx = t - yy * Wl[l];
    out[base + (size_t)idx * 2 + 0] = (float)(xx * Sl[l] + Sl[l] / 2);
    out[base + (size_t)idx * 2 + 1] = (float)(yy * Sl[l] + Sl[l] / 2);
}

// ---------------------------------------------------------------------------
// Host orchestration
// ---------------------------------------------------------------------------
extern "C" void kernel_launch(void* const* d_in, const int* in_sizes, int n_in,
                              void* d_out, int out_size)
{
    const float* feats[5] = {
        (const float*)d_in[0], (const float*)d_in[1], (const float*)d_in[2],
        (const float*)d_in[3], (const float*)d_in[4]};
    const float* cls_w    = (const float*)d_in[5];
    const float* cls_b    = (const float*)d_in[6];
    const float* cls_gn_g = (const float*)d_in[7];
    const float* cls_gn_b = (const float*)d_in[8];
    const float* box_w    = (const float*)d_in[9];
    const float* box_b    = (const float*)d_in[10];
    const float* box_gn_g = (const float*)d_in[11];
    const float* box_gn_b = (const float*)d_in[12];
    const float* logits_w = (const float*)d_in[13];
    const float* logits_b = (const float*)d_in[14];
    const float* ctr_w    = (const float*)d_in[15];
    const float* ctr_b    = (const float*)d_in[16];
    const float* reg_w    = (const float*)d_in[17];
    const float* reg_b    = (const float*)d_in[18];
    const float* scales   = (const float*)d_in[19];

    float *ycls, *ybox, *stats, *aff;
    __nv_bfloat16 *fh, *fl, *th, *tl, *wtc;
    cudaGetSymbolAddress((void**)&ycls, g_ycls);
    cudaGetSymbolAddress((void**)&ybox, g_ybox);
    cudaGetSymbolAddress((void**)&fh, g_fh);
    cudaGetSymbolAddress((void**)&fl, g_fl);
    cudaGetSymbolAddress((void**)&th, g_th);
    cudaGetSymbolAddress((void**)&tl, g_tl);
    cudaGetSymbolAddress((void**)&stats, g_stats);
    cudaGetSymbolAddress((void**)&aff, g_aff);
    cudaGetSymbolAddress((void**)&wtc, g_wtc);
    float* affA0 = aff;
    float* affS0 = aff + 2048;
    float* affA1 = aff + 4096;
    float* affS1 = aff + 6144;

    float* out = (float*)d_out;

    const int Hs[5] = {100, 50, 25, 13, 7};
    const int Ws[5] = {152, 76, 38, 19, 10};
    const size_t off85[5] = {0, 1292000, 1615000, 1695750, 1716745};
    const size_t TOT = 1722695;
    const size_t WLAY = (size_t)36 * 2 * 16384;      // bf16 per layer

    cudaFuncSetAttribute(conv_mma, cudaFuncAttributeMaxDynamicSharedMemorySize, DYN);

    // one-time weight reshape into bf16 hi/lo tiles (256-oc layout)
    reshape_wtc<<<(8*36*2*16384 + 255) / 256, 256>>>(cls_w, box_w, wtc);

    for (int l = 0; l < 5; l++) {
        const int H = Hs[l], W = Ws[l], HW = H * W;
        const int ntiles = (HW + 127) / 128;
        dim3 grid(ntiles, 8);
        dim3 gridS((HW + 31) / 32, 8);
        dim3 gridH((W + 7) / 8, (H + 7) / 8, 8);
        const float invCnt = 1.0f / (8.0f * (float)HW);

        split_act<<<gridS, 256>>>(feats[l], nullptr, nullptr, fh, fl, HW, 0);

        // ---- cls tower (layers 0-3, affine slot 0) ----
        {
            const __nv_bfloat16 *ch = fh, *cl = fl;
            for (int i = 0; i < 4; i++) {
                const __nv_bfloat16* wi = wtc + (size_t)i * WLAY;
                cudaMemsetAsync(stats, 0, 8 * 32 * 2 * sizeof(float), 0);
                conv_mma<<<grid, 256, DYN>>>(ch, cl, wi, cls_b + i * 256, ycls, stats, H, W);
                gn_finalize<<<8, 256>>>(stats, cls_gn_g + i * 256, cls_gn_b + i * 256,
                                        affA0, affS0, invCnt);
                if (i < 3) {
                    split_act<<<gridS, 256>>>(ycls, affA0, affS0, th, tl, HW, 1);
                    ch = th; cl = tl;
                }
            }
        }

        // ---- box tower (layers 4-7, affine slot 1) ----
        {
            const __nv_bfloat16 *ch = fh, *cl = fl;
            for (int i = 0; i < 4; i++) {
                const __nv_bfloat16* wi = wtc + (size_t)(4 + i) * WLAY;
                cudaMemsetAsync(stats, 0, 8 * 32 * 2 * sizeof(float), 0);
                conv_mma<<<grid, 256, DYN>>>(ch, cl, wi, box_b + i * 256, ybox, stats, H, W);
                gn_finalize<<<8, 256>>>(stats, box_gn_g + i * 256, box_gn_b + i * 256,
                                        affA1, affS1, invCnt);
                if (i < 3) {
                    split_act<<<gridS, 256>>>(ybox, affA1, affS1, th, tl, HW, 1);
                    ch = th; cl = tl;
                }
            }
        }

        // ---- heads: logits(80)@c0, reg(4)@c80 (exp), ctr(1)@c84 ----
        conv_head<<<gridH, 256>>>(ycls, logits_w, logits_b, affA0, affS0,
                                  out, off85[l], TOT, 0, 80, H, W, 0, scales, l);
        conv_head<<<gridH, 256>>>(ybox, reg_w, reg_b, affA1, affS1,
                                  out, off85[l], TOT, 80, 4, H, W, 1, scales, l);
        conv_head<<<gridH, 256>>>(ycls, ctr_w, ctr_b, affA0, affS0,
                                  out, off85[l], TOT, 84, 1, H, W, 0, scales, l);
    }

    locations_kernel<<<(20267 + 255) / 256, 256>>>(out, (size_t)8 * TOT);
}

// round 17
// speedup vs baseline: 1.1409x; 1.1267x over previous
#include <cuda_runtime.h>
#include <cuda_fp16.h>
#include <math.h>
#include <stdint.h>

// ---------------------------------------------------------------------------
// FCOS head. Tower convs (256->256, 3x3) as implicit GEMM on mma.sync fp16
// with 2-term weight split (w = wh + wl fp16; x single fp16):
//   y = (wh + wl) . x_fp16   -> error ~2^-12 (x rounding only), ~5e-4 e2e.
// CTA = 256oc x 128px, warp = 64oc x 64px. cp.async double-buffered fills.
// Activations pre-cast to transposed [b][px][256] fp16 by act_cast.
// ---------------------------------------------------------------------------

#define MAXBUF (8*256*15200)

__device__ float g_ycls[MAXBUF];
__device__ float g_ybox[MAXBUF];
__device__ __half g_f16[MAXBUF];                    // cast feats [b][px][256]
__device__ __half g_t16[MAXBUF];                    // cast tower act
__device__ float g_stats[8*32*2];
__device__ float g_aff[2][2][8*256];
__device__ __half g_wtc[8u*36u*2u*16384u];          // [lay][chunk][plane hi|lo][256oc x 64ic]

__device__ __forceinline__ uint32_t smem_u32(const void* p) {
    uint32_t a;
    asm("{ .reg .u64 t; cvta.to.shared.u64 t, %1; cvt.u32.u64 %0, t; }"
        : "=r"(a) : "l"(p));
    return a;
}
__device__ __forceinline__ void ldsm_x4(uint32_t& r0, uint32_t& r1,
                                        uint32_t& r2, uint32_t& r3, uint32_t addr) {
    asm volatile("ldmatrix.sync.aligned.m8n8.x4.shared.b16 {%0,%1,%2,%3}, [%4];"
                 : "=r"(r0), "=r"(r1), "=r"(r2), "=r"(r3) : "r"(addr));
}
__device__ __forceinline__ void mma_f16(float* c, const uint32_t* a,
                                        uint32_t b0, uint32_t b1) {
    asm volatile(
        "mma.sync.aligned.m16n8k16.row.col.f32.f16.f16.f32 "
        "{%0,%1,%2,%3}, {%4,%5,%6,%7}, {%8,%9}, {%0,%1,%2,%3};"
        : "+f"(c[0]), "+f"(c[1]), "+f"(c[2]), "+f"(c[3])
        : "r"(a[0]), "r"(a[1]), "r"(a[2]), "r"(a[3]), "r"(b0), "r"(b1));
}
__device__ __forceinline__ void cpa16(uint32_t dst, const void* src, uint32_t sz) {
    asm volatile("cp.async.ca.shared.global [%0], [%1], 16, %2;"
                 :: "r"(dst), "l"(src), "r"(sz) : "memory");
}
#define CPA_COMMIT() asm volatile("cp.async.commit_group;" ::: "memory")
#define CPA_WAIT0()  asm volatile("cp.async.wait_group 0;" ::: "memory")

#define PITCHB 144
#define ABYTES 73728              // 2 planes x 256 rows x 144
#define BBYTES 18432              // 1 plane  x 128 rows x 144
#define BUFSZ  92160              // ABYTES + BBYTES
#define DYN    (2*BUFSZ + 1024)

// ---------------------------------------------------------------------------
// Weight reshape: fp32 w[lay][oc][ic*9+k] -> fp16 hi/lo planes:
// g_wtc[((lay*36+chunk)*2+plane)*16384 + oc*64 + ic_c], chunk = k*4 + icc.
// ---------------------------------------------------------------------------
__global__ void reshape_wtc(const float* __restrict__ cls_w,
                            const float* __restrict__ box_w,
                            __half* __restrict__ out)
{
    unsigned idx = blockIdx.x * blockDim.x + threadIdx.x;   // 9,437,184
    if (idx >= 8u*36u*2u*16384u) return;
    unsigned e = idx & 16383u;
    unsigned oc = e >> 6, ic_c = e & 63u;
    unsigned t = idx >> 14;
    unsigned plane = t & 1u; t >>= 1;
    unsigned chunk = t % 36u;
    unsigned lay = t / 36u;
    unsigned k = chunk >> 2, icc = chunk & 3u;
    const float* src = (lay < 4) ? cls_w : box_w;
    unsigned l = lay & 3u;
    unsigned ic = icc * 64u + ic_c;
    float w = src[(size_t)l * 256u * 2304u + (size_t)oc * 2304u + ic * 9u + k];
    __half hi = __float2half(w);
    __half lo = __float2half(w - __half2float(hi));
    out[idx] = plane ? lo : hi;
}

// ---------------------------------------------------------------------------
// act_cast: y [b][c][HW] fp32 -> (affine+relu if useAff) -> fp16,
// transposed [b][px][256]. Block 256, grid (ceil(HW/32), 8).
// ---------------------------------------------------------------------------
__global__ __launch_bounds__(256) void act_cast(
    const float* __restrict__ y,
    const float* __restrict__ affA, const float* __restrict__ affS,
    __half* __restrict__ oh, int HW, int useAff)
{
    __shared__ float t[256][33];
    const int b  = blockIdx.y;
    const int p0 = blockIdx.x << 5;
    const int tid = threadIdx.x;
    {
        int cr = tid >> 5, pr = tid & 31;
        int p = p0 + pr;
        #pragma unroll 4
        for (int i = 0; i < 32; i++) {
            int c = cr + (i << 3);
            t[c][pr] = (p < HW) ? y[((size_t)b * 256 + c) * HW + p] : 0.f;
        }
    }
    __syncthreads();
    {
        int pw = tid >> 3, c0 = (tid & 7) << 5;
        int p = p0 + pw;
        if (p < HW) {
            size_t ob = ((size_t)b * HW + p) * 256;
            #pragma unroll 8
            for (int c = c0; c < c0 + 32; c += 2) {
                float v0 = t[c][pw], v1 = t[c + 1][pw];
                if (useAff) {
                    v0 = fmaxf(fmaf(affA[b * 256 + c],     v0, affS[b * 256 + c]),     0.f);
                    v1 = fmaxf(fmaf(affA[b * 256 + c + 1], v1, affS[b * 256 + c + 1]), 0.f);
                }
                *(__half2*)(oh + ob + c) = __half2(__float2half(v0), __float2half(v1));
            }
        }
    }
}

// ---------------------------------------------------------------------------
// Fill one buffer with chunk data via cp.async (A: weights hi/lo, B: act fp16).
// ---------------------------------------------------------------------------
__device__ __forceinline__ void fill_chunk(
    uint32_t uBuf, int tid, int chunk,
    const __half* __restrict__ wt, const __half* __restrict__ xh,
    const int* hh4, const int* ww4, const int* pp4, const unsigned* inb4,
    int b, int HW, int H, int W)
{
    // A: 16 segs/thread (2 planes x 256 rows x 8 segs)
    const __half* wc = wt + ((size_t)chunk << 15);
    #pragma unroll
    for (int i = 0; i < 16; i++) {
        int plane = i >> 3;
        int row = (tid >> 3) + ((i & 7) << 5);
        int s8 = tid & 7;
        uint32_t dst = uBuf + plane * 36864 + row * PITCHB + (s8 << 4);
        cpa16(dst, wc + (plane << 14) + (row << 6) + (s8 << 3), 16);
    }
    // B: 4 segs/thread (1 plane x 128 rows), rows g+{0,32,64,96}
    const int k  = chunk >> 2;
    const int dh = k / 3 - 1, dw = k - (k / 3) * 3 - 1;
    const int ic0 = (chunk & 3) << 6;
    const int s8 = tid & 7;
    #pragma unroll
    for (int q = 0; q < 4; q++) {
        int row = (tid >> 3) + (q << 5);
        int h2 = hh4[q] + dh, w2 = ww4[q] + dw;
        unsigned valid = inb4[q] && (unsigned)h2 < (unsigned)H && (unsigned)w2 < (unsigned)W;
        const __half* src = xh + ((size_t)(b * HW + (valid ? (pp4[q] + dh * W + dw) : 0)) << 8)
                            + ic0 + (s8 << 3);
        uint32_t dst = uBuf + ABYTES + row * PITCHB + (s8 << 4);
        cpa16(dst, src, valid ? 16u : 0u);
    }
    CPA_COMMIT();
}

// ---------------------------------------------------------------------------
// Tower conv. Block 256 (8 warps), grid (ceil(HW/128), 8). CTA = 256oc x 128px.
// Warp = 64oc x 64px (mt=4, nt=8). 2-term fp16: acc += wh.x ; acc += wl.x.
// ---------------------------------------------------------------------------
__global__ __launch_bounds__(256)
void conv_mma(const __half* __restrict__ xh,
              const __half* __restrict__ wt,
              const float* __restrict__ bias,
              float* __restrict__ y, float* __restrict__ stats, int H, int W)
{
    extern __shared__ char dsm[];
    const int HW = H * W;
    const int b  = blockIdx.y;
    const int p0 = blockIdx.x << 7;
    const int tid = threadIdx.x, wid = tid >> 5, lane = tid & 31;

    uint32_t sraw = smem_u32(dsm);
    uint32_t sb = (sraw + 1023u) & ~1023u;
    char* base = dsm + (sb - sraw);
    float* s_out = (float*)base;               // 256 x 132 fp32 after compute

    int hh4[4], ww4[4], pp4[4];
    unsigned inb4[4];
    #pragma unroll
    for (int q = 0; q < 4; q++) {
        int row = (tid >> 3) + (q << 5);
        int p = p0 + row;
        pp4[q] = p;
        inb4[q] = (p < HW);
        int h = p / W;
        hh4[q] = h;
        ww4[q] = p - h * W;
    }

    const int warp_m = wid & 3;     // 4 x 64 oc
    const int warp_n = wid >> 2;    // 2 x 64 px
    const int a_row = lane & 15, a_k8 = lane >> 4;
    const int b_sel = lane >> 3, b_row = lane & 7;

    float acc[4][8][4];
    #pragma unroll
    for (int mt = 0; mt < 4; mt++)
        #pragma unroll
        for (int nt = 0; nt < 8; nt++)
            #pragma unroll
            for (int q = 0; q < 4; q++) acc[mt][nt][q] = 0.f;

    fill_chunk(sb, tid, 0, wt, xh, hh4, ww4, pp4, inb4, b, HW, H, W);

    for (int chunk = 0; chunk < 36; chunk++) {
        CPA_WAIT0();
        __syncthreads();
        if (chunk + 1 < 36)
            fill_chunk(sb + ((chunk + 1) & 1) * BUFSZ, tid, chunk + 1,
                       wt, xh, hh4, ww4, pp4, inb4, b, HW, H, W);

        const uint32_t uA = sb + (chunk & 1) * BUFSZ;
        const uint32_t uB = uA + ABYTES;

        #pragma unroll
        for (int ks = 0; ks < 4; ks++) {
            uint32_t ah[4][4], al[4][4];
            const uint32_t koffA = ((ks << 4) + (a_k8 << 3)) << 1;
            #pragma unroll
            for (int mt = 0; mt < 4; mt++) {
                uint32_t arow = warp_m * 64 + mt * 16 + a_row;
                ldsm_x4(ah[mt][0], ah[mt][1], ah[mt][2], ah[mt][3],
                        uA + arow * PITCHB + koffA);
                ldsm_x4(al[mt][0], al[mt][1], al[mt][2], al[mt][3],
                        uA + 36864 + arow * PITCHB + koffA);
            }
            const uint32_t koffB = ((ks << 4) + ((b_sel & 1) << 3)) << 1;
            #pragma unroll
            for (int half = 0; half < 4; half++) {
                uint32_t nrow = warp_n * 64 + half * 16 + ((b_sel >> 1) << 3) + b_row;
                uint32_t bh[4];
                ldsm_x4(bh[0], bh[1], bh[2], bh[3], uB + nrow * PITCHB + koffB);
                #pragma unroll
                for (int par = 0; par < 2; par++) {
                    const int nt = half * 2 + par;
                    uint32_t b0 = bh[par * 2], b1 = bh[par * 2 + 1];
                    #pragma unroll
                    for (int mt = 0; mt < 4; mt++)
                        mma_f16(acc[mt][nt], ah[mt], b0, b1);
                    #pragma unroll
                    for (int mt = 0; mt < 4; mt++)
                        mma_f16(acc[mt][nt], al[mt], b0, b1);
                }
            }
        }
        __syncthreads();
    }

    // ---- epilogue: acc + bias -> s_out (256 x 132) -> stats -> store ----
    #pragma unroll
    for (int mt = 0; mt < 4; mt++) {
        int r1 = warp_m * 64 + mt * 16 + (lane >> 2);
        int r2 = r1 + 8;
        float bv1 = __ldg(bias + r1);
        float bv2 = __ldg(bias + r2);
        #pragma unroll
        for (int nt = 0; nt < 8; nt++) {
            int cb = warp_n * 64 + nt * 8 + ((lane & 3) << 1);
            s_out[r1 * 132 + cb]     = acc[mt][nt][0] + bv1;
            s_out[r1 * 132 + cb + 1] = acc[mt][nt][1] + bv1;
            s_out[r2 * 132 + cb]     = acc[mt][nt][2] + bv2;
            s_out[r2 * 132 + cb + 1] = acc[mt][nt][3] + bv2;
        }
    }
    __syncthreads();

    {
        float lsum = 0.f, lsq = 0.f;
        #pragma unroll 8
        for (int col = 0; col < 128; col++) {
            if (p0 + col < HW) {
                float v = s_out[tid * 132 + col];
                lsum += v; lsq += v * v;
            }
        }
        lsum += __shfl_xor_sync(0xffffffffu, lsum, 1);
        lsq  += __shfl_xor_sync(0xffffffffu, lsq,  1);
        lsum += __shfl_xor_sync(0xffffffffu, lsum, 2);
        lsq  += __shfl_xor_sync(0xffffffffu, lsq,  2);
        lsum += __shfl_xor_sync(0xffffffffu, lsum, 4);
        lsq  += __shfl_xor_sync(0xffffffffu, lsq,  4);
        if ((lane & 7) == 0) {
            int g = tid >> 3;
            atomicAdd(&stats[(b * 32 + g) * 2 + 0], lsum);
            atomicAdd(&stats[(b * 32 + g) * 2 + 1], lsq);
        }
    }
    for (int i = 0; i < 128; i++) {
        int idx  = tid + (i << 8);
        int oc = idx >> 7, jj = idx & 127;
        int pp = p0 + jj;
        if (pp < HW)
            y[(((size_t)b << 8) + oc) * HW + pp] = s_out[oc * 132 + jj];
    }
}

// ---------------------------------------------------------------------------
// GN finalize: stats -> per-channel affine (a, s).
// ---------------------------------------------------------------------------
__global__ void gn_finalize(const float* __restrict__ stats,
                            const float* __restrict__ gamma,
                            const float* __restrict__ beta,
                            float* __restrict__ affA, float* __restrict__ affS,
                            float invCnt)
{
    int b = blockIdx.x;
    int c = threadIdx.x;
    int g = c >> 3;
    float sum = stats[(b * 32 + g) * 2 + 0];
    float sq  = stats[(b * 32 + g) * 2 + 1];
    float m   = sum * invCnt;
    float var = fmaf(sq, invCnt, -m * m);
    float rstd = rsqrtf(var + 1e-5f);
    float a = gamma[c] * rstd;
    affA[b * 256 + c] = a;
    affS[b * 256 + c] = fmaf(-m, a, beta[c]);
}

// ---------------------------------------------------------------------------
// Head conv: IC=256, OC in {80,1,4}. Affine+relu input. Direct final layout.
// ---------------------------------------------------------------------------
__global__ __launch_bounds__(256) void conv_head(
    const float* __restrict__ x, const float* __restrict__ w,
    const float* __restrict__ bias,
    const float* __restrict__ affA, const float* __restrict__ affS,
    float* __restrict__ out, size_t lvlOff, size_t TOT, int cbase,
    int OC, int H, int W, int doExp, const float* __restrict__ scales, int lvl)
{
    const int HW = H * W;
    const int b  = blockIdx.z;
    const int h0 = blockIdx.y << 3, w0 = blockIdx.x << 3;
    const int tid  = threadIdx.x;
    const int lane = tid & 3;
    const int pp   = tid >> 2;
    const int ph = pp >> 3, pw = pp & 7;

    __shared__ float s_in[8][10][12];
    __shared__ float s_w[8][9][80];

    float acc[20];
    const int noc = (OC + 3) >> 2;
    #pragma unroll
    for (int jj = 0; jj < 20; jj++) acc[jj] = 0.f;

    const float* xb = x + (size_t)b * 256 * HW;
    const float* aA = affA + b * 256;
    const float* aS = affS + b * 256;

    for (int c0 = 0; c0 < 256; c0 += 8) {
        for (int idx = tid; idx < 800; idx += 256) {
            int ic = idx / 100; int rr = idx - ic * 100;
            int r = rr / 10;    int c  = rr - r * 10;
            int ih = h0 - 1 + r, iw = w0 - 1 + c;
            float v = 0.f;
            if ((unsigned)ih < (unsigned)H && (unsigned)iw < (unsigned)W) {
                v = xb[(size_t)(c0 + ic) * HW + ih * W + iw];
                v = fmaxf(fmaf(aA[c0 + ic], v, aS[c0 + ic]), 0.f);
            }
            s_in[ic][r][c] = v;
        }
        int nw = OC * 72;
        for (int idx = tid; idx < nw; idx += 256) {
            int oc = idx / 72; int rem = idx - oc * 72;
            int ic = rem / 9;  int k   = rem - ic * 9;
            s_w[ic][k][oc] = w[(size_t)oc * 2304 + (c0 + ic) * 9 + k];
        }
        __syncthreads();

        #pragma unroll 2
        for (int ic = 0; ic < 8; ic++) {
            #pragma unroll
            for (int kh = 0; kh < 3; kh++) {
                #pragma unroll
                for (int kw = 0; kw < 3; kw++) {
                    float xv = s_in[ic][ph + kh][pw + kw];
                    int k = kh * 3 + kw;
                    for (int jj = 0; jj < noc; jj++)
                        acc[jj] = fmaf(xv, s_w[ic][k][(jj << 2) + lane], acc[jj]);
                }
            }
        }
        __syncthreads();
    }

    int hh = h0 + ph, ww = w0 + pw;
    if (hh < H && ww < W) {
        float sc = doExp ? scales[lvl] : 0.f;
        for (int jj = 0; jj < noc; jj++) {
            int oc = (jj << 2) + lane;
            if (oc < OC) {
                float v = acc[jj] + bias[oc];
                if (doExp) v = expf(sc * v);
                out[(size_t)b * TOT + lvlOff + (size_t)(cbase + oc) * HW + hh * W + ww] = v;
            }
        }
    }
}

// ---------------------------------------------------------------------------
// FCOS grid locations.
// ---------------------------------------------------------------------------
__global__ void locations_kernel(float* __restrict__ out, size_t base)
{
    const int Wl[5] = {152, 76, 38, 19, 10};
    const int Sl[5] = {8, 16, 32, 64, 128};
    const int sizes[5] = {15200, 3800, 950, 247, 70};
    int idx = blockIdx.x * blockDim.x + threadIdx.x;
    if (idx >= 20267) return;
    int l = 0, t = idx;
    while (l < 4 && t >= sizes[l]) { t -= sizes[l]; l++; }
    int yy = t / Wl[l], xx = t - yy * Wl[l];
    out[base + (size_t)idx * 2 + 0] = (float)(xx * Sl[l] + Sl[l] / 2);
    out[base + (size_t)idx * 2 + 1] = (float)(yy * Sl[l] + Sl[l] / 2);
}

// ---------------------------------------------------------------------------
// Host orchestration
// ---------------------------------------------------------------------------
extern "C" void kernel_launch(void* const* d_in, const int* in_sizes, int n_in,
                              void* d_out, int out_size)
{
    const float* feats[5] = {
        (const float*)d_in[0], (const float*)d_in[1], (const float*)d_in[2],
        (const float*)d_in[3], (const float*)d_in[4]};
    const float* cls_w    = (const float*)d_in[5];
    const float* cls_b    = (const float*)d_in[6];
    const float* cls_gn_g = (const float*)d_in[7];
    const float* cls_gn_b = (const float*)d_in[8];
    const float* box_w    = (const float*)d_in[9];
    const float* box_b    = (const float*)d_in[10];
    const float* box_gn_g = (const float*)d_in[11];
    const float* box_gn_b = (const float*)d_in[12];
    const float* logits_w = (const float*)d_in[13];
    const float* logits_b = (const float*)d_in[14];
    const float* ctr_w    = (const float*)d_in[15];
    const float* ctr_b    = (const float*)d_in[16];
    const float* reg_w    = (const float*)d_in[17];
    const float* reg_b    = (const float*)d_in[18];
    const float* scales   = (const float*)d_in[19];

    float *ycls, *ybox, *stats, *aff;
    __half *f16, *t16, *wtc;
    cudaGetSymbolAddress((void**)&ycls, g_ycls);
    cudaGetSymbolAddress((void**)&ybox, g_ybox);
    cudaGetSymbolAddress((void**)&f16, g_f16);
    cudaGetSymbolAddress((void**)&t16, g_t16);
    cudaGetSymbolAddress((void**)&stats, g_stats);
    cudaGetSymbolAddress((void**)&aff, g_aff);
    cudaGetSymbolAddress((void**)&wtc, g_wtc);
    float* affA0 = aff;
    float* affS0 = aff + 2048;
    float* affA1 = aff + 4096;
    float* affS1 = aff + 6144;

    float* out = (float*)d_out;

    const int Hs[5] = {100, 50, 25, 13, 7};
    const int Ws[5] = {152, 76, 38, 19, 10};
    const size_t off85[5] = {0, 1292000, 1615000, 1695750, 1716745};
    const size_t TOT = 1722695;
    const size_t WLAY = (size_t)36 * 2 * 16384;      // fp16 per layer

    cudaFuncSetAttribute(conv_mma, cudaFuncAttributeMaxDynamicSharedMemorySize, DYN);

    reshape_wtc<<<(8*36*2*16384 + 255) / 256, 256>>>(cls_w, box_w, wtc);

    for (int l = 0; l < 5; l++) {
        const int H = Hs[l], W = Ws[l], HW = H * W;
        const int ntiles = (HW + 127) / 128;
        dim3 grid(ntiles, 8);
        dim3 gridS((HW + 31) / 32, 8);
        dim3 gridH((W + 7) / 8, (H + 7) / 8, 8);
        const float invCnt = 1.0f / (8.0f * (float)HW);

        act_cast<<<gridS, 256>>>(feats[l], nullptr, nullptr, f16, HW, 0);

        // ---- cls tower (layers 0-3, affine slot 0) ----
        {
            const __half* ch = f16;
            for (int i = 0; i < 4; i++) {
                const __half* wi = wtc + (size_t)i * WLAY;
                cudaMemsetAsync(stats, 0, 8 * 32 * 2 * sizeof(float), 0);
                conv_mma<<<grid, 256, DYN>>>(ch, wi, cls_b + i * 256, ycls, stats, H, W);
                gn_finalize<<<8, 256>>>(stats, cls_gn_g + i * 256, cls_gn_b + i * 256,
                                        affA0, affS0, invCnt);
                if (i < 3) {
                    act_cast<<<gridS, 256>>>(ycls, affA0, affS0, t16, HW, 1);
                    ch = t16;
                }
            }
        }

        // ---- box tower (layers 4-7, affine slot 1) ----
        {
            const __half* ch = f16;
            for (int i = 0; i < 4; i++) {
                const __half* wi = wtc + (size_t)(4 + i) * WLAY;
                cudaMemsetAsync(stats, 0, 8 * 32 * 2 * sizeof(float), 0);
                conv_mma<<<grid, 256, DYN>>>(ch, wi, box_b + i * 256, ybox, stats, H, W);
                gn_finalize<<<8, 256>>>(stats, box_gn_g + i * 256, box_gn_b + i * 256,
                                        affA1, affS1, invCnt);
                if (i < 3) {
                    act_cast<<<gridS, 256>>>(ybox, affA1, affS1, t16, HW, 1);
                    ch = t16;
                }
            }
        }

        // ---- heads: logits(80)@c0, reg(4)@c80 (exp), ctr(1)@c84 ----
        conv_head<<<gridH, 256>>>(ycls, logits_w, logits_b, affA0, affS0,
                                  out, off85[l], TOT, 0, 80, H, W, 0, scales, l);
        conv_head<<<gridH, 256>>>(ybox, reg_w, reg_b, affA1, affS1,
                                  out, off85[l], TOT, 80, 4, H, W, 1, scales, l);
        conv_head<<<gridH, 256>>>(ycls, ctr_w, ctr_b, affA0, affS0,
                                  out, off85[l], TOT, 84, 1, H, W, 0, scales, l);
    }

    locations_kernel<<<(20267 + 255) / 256, 256>>>(out, (size_t)8 * TOT);
}